// round 1
// baseline (speedup 1.0000x reference)
#include <cuda_runtime.h>

// DegreePrediction: y[u] = sum_{s,t,v} (x*W_t)[s,t] * (W_r*r_zeros + r_const)[s,t,u,v]
// N = 80. Pure HBM-streaming reduction over three 80^4 fp32 tensors (491.5 MB).
//
// Layout facts used:
//   - slice (s,t) is 6400 contiguous floats = 1600 float4
//   - u-row inside a slice is 80 contiguous floats = 20 float4
//   - with 320 threads, iteration j reads float4 index p = tid + 320*j,
//     which is fully contiguous across the block AND each thread's float4
//     stays inside a single u-row: u = tid/20 + 16*j (constant per thread/j).

#define NN 80
#define SLICE_FLOATS (NN * NN)      // 6400
#define THREADS 320
#define J_ITERS 5                   // 1600 float4 / 320 threads
#define K_SLICES 4
#define NUM_BLOCKS ((NN * NN) / K_SLICES)   // 1600

__global__ void zero_out_kernel(float* __restrict__ out) {
    int i = threadIdx.x;
    if (i < NN) out[i] = 0.0f;
}

__global__ __launch_bounds__(THREADS)
void degree_pred_kernel(const float* __restrict__ x,
                        const float* __restrict__ r_zeros,
                        const float* __restrict__ r_const,
                        const float* __restrict__ weights_t,
                        const float* __restrict__ weights_r,
                        float* __restrict__ out)
{
    __shared__ float y_sh[NN];
    const int tid = threadIdx.x;
    if (tid < NN) y_sh[tid] = 0.0f;

    // 5 float4 accumulators, one per j (fixed u per (thread, j))
    float4 acc[J_ITERS];
#pragma unroll
    for (int j = 0; j < J_ITERS; j++) acc[j] = make_float4(0.f, 0.f, 0.f, 0.f);

    const int st0 = blockIdx.x * K_SLICES;

#pragma unroll
    for (int k = 0; k < K_SLICES; k++) {
        const int st = st0 + k;
        const float a = __ldg(&x[st]) * __ldg(&weights_t[st]);
        const size_t base = (size_t)st * SLICE_FLOATS;
        const float4* __restrict__ rz = reinterpret_cast<const float4*>(r_zeros   + base);
        const float4* __restrict__ rc = reinterpret_cast<const float4*>(r_const   + base);
        const float4* __restrict__ wr = reinterpret_cast<const float4*>(weights_r + base);

#pragma unroll
        for (int j = 0; j < J_ITERS; j++) {
            const int p = tid + THREADS * j;
            const float4 z = __ldg(&rz[p]);
            const float4 c = __ldg(&rc[p]);
            const float4 w = __ldg(&wr[p]);
            acc[j].x += a * fmaf(w.x, z.x, c.x);
            acc[j].y += a * fmaf(w.y, z.y, c.y);
            acc[j].z += a * fmaf(w.z, z.z, c.z);
            acc[j].w += a * fmaf(w.w, z.w, c.w);
        }
    }

    __syncthreads();

    const int u0 = tid / 20;   // 20 float4 per u-row
#pragma unroll
    for (int j = 0; j < J_ITERS; j++) {
        const float s = (acc[j].x + acc[j].y) + (acc[j].z + acc[j].w);
        atomicAdd(&y_sh[u0 + 16 * j], s);
    }

    __syncthreads();
    if (tid < NN) atomicAdd(&out[tid], y_sh[tid]);
}

extern "C" void kernel_launch(void* const* d_in, const int* in_sizes, int n_in,
                              void* d_out, int out_size)
{
    const float* x         = (const float*)d_in[0];
    const float* r_zeros   = (const float*)d_in[1];
    const float* r_const   = (const float*)d_in[2];
    const float* weights_t = (const float*)d_in[3];
    const float* weights_r = (const float*)d_in[4];
    float* out = (float*)d_out;

    zero_out_kernel<<<1, 128>>>(out);
    degree_pred_kernel<<<NUM_BLOCKS, THREADS>>>(x, r_zeros, r_const,
                                                weights_t, weights_r, out);
}

// round 2
// speedup vs baseline: 1.0080x; 1.0080x over previous
#include <cuda_runtime.h>

// DegreePrediction: y[u] = sum_{s,t,v} (x*W_t)[s,t] * (W_r*r_zeros + r_const)[s,t,u,v]
// N = 80. Pure HBM-streaming reduction over three 80^4 fp32 tensors (491.5 MB).
//
// R2 change vs R1: scalar accumulators (fold the float4 lanes into the running
// sum immediately) + __launch_bounds__(320,5) to lift occupancy 3->5 blocks/SM,
// + __ldcs streaming loads. Targets the latency-exposed DRAM regime seen in ncu
// (DRAM 68%, occ 43%, 57 regs).
//
// Layout facts used:
//   - slice (s,t) is 6400 contiguous floats = 1600 float4
//   - u-row inside a slice is 80 contiguous floats = 20 float4
//   - with 320 threads, iteration j reads float4 index p = tid + 320*j,
//     fully coalesced across the block, and each thread's float4 stays inside
//     a single u-row: u = tid/20 + 16*j (constant per thread/j).

#define NN 80
#define SLICE_FLOATS (NN * NN)      // 6400
#define THREADS 320
#define J_ITERS 5                   // 1600 float4 / 320 threads
#define K_SLICES 4
#define NUM_BLOCKS ((NN * NN) / K_SLICES)   // 1600

__global__ void zero_out_kernel(float* __restrict__ out) {
    int i = threadIdx.x;
    if (i < NN) out[i] = 0.0f;
}

__global__ __launch_bounds__(THREADS, 5)
void degree_pred_kernel(const float* __restrict__ x,
                        const float* __restrict__ r_zeros,
                        const float* __restrict__ r_const,
                        const float* __restrict__ weights_t,
                        const float* __restrict__ weights_r,
                        float* __restrict__ out)
{
    __shared__ float y_sh[NN];
    const int tid = threadIdx.x;
    if (tid < NN) y_sh[tid] = 0.0f;

    // one scalar accumulator per j (fixed u per (thread, j))
    float acc[J_ITERS];
#pragma unroll
    for (int j = 0; j < J_ITERS; j++) acc[j] = 0.0f;

    const int st0 = blockIdx.x * K_SLICES;

#pragma unroll
    for (int k = 0; k < K_SLICES; k++) {
        const int st = st0 + k;
        const float a = __ldg(&x[st]) * __ldg(&weights_t[st]);
        const size_t base = (size_t)st * SLICE_FLOATS;
        const float4* __restrict__ rz = reinterpret_cast<const float4*>(r_zeros   + base);
        const float4* __restrict__ rc = reinterpret_cast<const float4*>(r_const   + base);
        const float4* __restrict__ wr = reinterpret_cast<const float4*>(weights_r + base);

#pragma unroll
        for (int j = 0; j < J_ITERS; j++) {
            const int p = tid + THREADS * j;
            const float4 z = __ldcs(&rz[p]);
            const float4 c = __ldcs(&rc[p]);
            const float4 w = __ldcs(&wr[p]);
            float t = (c.x + c.y) + (c.z + c.w);
            t = fmaf(w.x, z.x, t);
            t = fmaf(w.y, z.y, t);
            t = fmaf(w.z, z.z, t);
            t = fmaf(w.w, z.w, t);
            acc[j] = fmaf(a, t, acc[j]);
        }
    }

    __syncthreads();

    const int u0 = tid / 20;   // 20 float4 per u-row
#pragma unroll
    for (int j = 0; j < J_ITERS; j++) {
        atomicAdd(&y_sh[u0 + 16 * j], acc[j]);
    }

    __syncthreads();
    if (tid < NN) atomicAdd(&out[tid], y_sh[tid]);
}

extern "C" void kernel_launch(void* const* d_in, const int* in_sizes, int n_in,
                              void* d_out, int out_size)
{
    const float* x         = (const float*)d_in[0];
    const float* r_zeros   = (const float*)d_in[1];
    const float* r_const   = (const float*)d_in[2];
    const float* weights_t = (const float*)d_in[3];
    const float* weights_r = (const float*)d_in[4];
    float* out = (float*)d_out;

    zero_out_kernel<<<1, 128>>>(out);
    degree_pred_kernel<<<NUM_BLOCKS, THREADS>>>(x, r_zeros, r_const,
                                                weights_t, weights_r, out);
}